// round 1
// baseline (speedup 1.0000x reference)
#include <cuda_runtime.h>
#include <math.h>

#define NN      1024
#define KNN     8
#define D_IN    36
#define NPAIR   (NN*(NN-1)/2)    // 523776
#define EPSV    1e-5f
#define SLOPE   0.01f

// ---------------- device scratch (no allocations allowed) ----------------
__device__ float g_node[NN*100];          // [x(36) | e1(32) | e2(32)] per node
__device__ float g_mean[D_IN], g_scale[D_IN];
__device__ int   g_idx[NN*KNN];
__device__ float g_w1t1[288*32];          // ec1_w1 transposed  [t][o]
__device__ float g_w1t2[256*32];          // ec2_w1 transposed  [t][o]
__device__ float g_m1[100], g_s1[100], g_m2[100], g_s2[100];
__device__ float g_W1p[200*32];           // BN-scaled l_w1, layout [f][o]
__device__ float g_c[32];                 // folded bias for first pair layer
__device__ float g_A[NN*32];
__device__ float g_B[NN*32];

__device__ __forceinline__ float leaky(float x){ return fmaxf(x,0.f) + SLOPE*fminf(x,0.f); }
__device__ __forceinline__ int rowstart(int i){ return i*NN - ((i*(i+1))>>1); }

// ---------------- 1) BN stats over feat columns ----------------
__global__ void k_bn_stats(const float* __restrict__ feat){
    int f = blockIdx.x;
    __shared__ float ss[256], sq[256];
    float s=0.f, q=0.f;
    for(int i=threadIdx.x;i<NN;i+=256){ float v=feat[i*D_IN+f]; s+=v; q+=v*v; }
    ss[threadIdx.x]=s; sq[threadIdx.x]=q; __syncthreads();
    for(int o=128;o>0;o>>=1){
        if(threadIdx.x<o){ ss[threadIdx.x]+=ss[threadIdx.x+o]; sq[threadIdx.x]+=sq[threadIdx.x+o]; }
        __syncthreads();
    }
    if(threadIdx.x==0){
        float m=ss[0]*(1.f/NN);
        float var=sq[0]*(1.f/NN)-m*m;
        g_mean[f]=m; g_scale[f]=rsqrtf(var+EPSV);
    }
}

// ---------------- 2) normalize x into g_node; also emit cells ----------------
__global__ void k_norm(const float* __restrict__ feat, const float* __restrict__ bng,
                       const float* __restrict__ bnb, float* __restrict__ out_cells){
    int t = blockIdx.x*blockDim.x + threadIdx.x;
    if (t < NN*D_IN){
        int i=t/D_IN, f=t%D_IN;
        g_node[i*100+f] = (feat[t]-g_mean[f])*g_scale[f]*bng[f]+bnb[f];
    }
    if (t < NN*5){
        int i=t/5, c=t%5;
        out_cells[i*5+c] = feat[i*D_IN+c];
    }
}

// ---------------- 3) transpose edge-conv first-layer weights ----------------
__global__ void k_transpose(const float* __restrict__ w1, const float* __restrict__ w2){
    int t = blockIdx.x*blockDim.x+threadIdx.x;
    if (t < 288*32){ int r=t>>5, o=t&31; g_w1t1[t] = w1[o*288+r]; }
    if (t < 256*32){ int r=t>>5, o=t&31; g_w1t2[t] = w2[o*256+r]; }
}

// ---------------- 4) kNN (top-8 smallest L1 dist over first 4 normalized feats) ----
// one warp per row; stable tie-break (d asc, idx asc) == jax.lax.top_k on -d
__global__ void k_knn(){
    int warp = (blockIdx.x*blockDim.x + threadIdx.x)>>5;
    int lane = threadIdx.x & 31;
    if (warp >= NN) return;
    const float4 xi = *(const float4*)(g_node + warp*100);
    float d8[8]; int id8[8];
#pragma unroll
    for(int k=0;k<8;k++){ d8[k]=3.4e38f; id8[k]=0x7fffffff; }
    for(int it=0; it<NN/32; it++){
        int j = lane + it*32;
        float4 xj = *(const float4*)(g_node + j*100);
        float d = fabsf(xi.x-xj.x)+fabsf(xi.y-xj.y)+fabsf(xi.z-xj.z)+fabsf(xi.w-xj.w);
        float cd=d; int ci=j;
#pragma unroll
        for(int k=0;k<8;k++){
            bool sw = (cd < d8[k]) || (cd==d8[k] && ci < id8[k]);
            float td = sw ? d8[k] : cd; int ti = sw ? id8[k] : ci;
            d8[k]  = sw ? cd : d8[k]; id8[k] = sw ? ci : id8[k];
            cd=td; ci=ti;
        }
    }
    // merge 32 sorted-8 lists: 8 rounds of warp argmin on (d, idx)
    for(int r=0;r<8;r++){
        float bd=d8[0]; int bi=id8[0];
#pragma unroll
        for(int off=16;off>0;off>>=1){
            float od=__shfl_xor_sync(0xffffffffu,bd,off);
            int   oi=__shfl_xor_sync(0xffffffffu,bi,off);
            if (od<bd || (od==bd && oi<bi)){ bd=od; bi=oi; }
        }
        if (lane==0) g_idx[warp*KNN+r]=bi;
        if (id8[0]==bi){
#pragma unroll
            for(int k=0;k<7;k++){ d8[k]=d8[k+1]; id8[k]=id8[k+1]; }
            d8[7]=3.4e38f; id8[7]=0x7fffffff;
        }
    }
}

// ---------------- 5) edge conv 1: gather x[idx] (f-major,k-minor) -> MLP -> e1 ----
__global__ void k_edge1(const float* __restrict__ b1, const float* __restrict__ w2,
                        const float* __restrict__ b2){
    __shared__ float sv[8][288];
    __shared__ float sh[8][32];
    int w = threadIdx.x>>5, lane = threadIdx.x&31;
    int node = blockIdx.x*8 + w;
    for(int t=lane;t<288;t+=32){
        int f=t>>3, k=t&7;
        sv[w][t] = g_node[g_idx[node*KNN+k]*100 + f];
    }
    __syncwarp();
    float acc = b1[lane];
    for(int t=0;t<288;t++) acc += g_w1t1[t*32+lane]*sv[w][t];
    sh[w][lane]=leaky(acc);
    __syncwarp();
    float acc2 = b2[lane];
#pragma unroll
    for(int f=0;f<32;f++) acc2 += w2[lane*32+f]*sh[w][f];
    g_node[node*100+36+lane]=leaky(acc2);
}

// ---------------- 6) edge conv 2: gather e1[idx] -> MLP -> e2 ----------------
__global__ void k_edge2(const float* __restrict__ b1, const float* __restrict__ w2,
                        const float* __restrict__ b2){
    __shared__ float sv[8][256];
    __shared__ float sh[8][32];
    int w = threadIdx.x>>5, lane = threadIdx.x&31;
    int node = blockIdx.x*8 + w;
    for(int t=lane;t<256;t+=32){
        int f=t>>3, k=t&7;
        sv[w][t] = g_node[g_idx[node*KNN+k]*100 + 36 + f];
    }
    __syncwarp();
    float acc = b1[lane];
    for(int t=0;t<256;t++) acc += g_w1t2[t*32+lane]*sv[w][t];
    sh[w][lane]=leaky(acc);
    __syncwarp();
    float acc2 = b2[lane];
#pragma unroll
    for(int f=0;f<32;f++) acc2 += w2[lane*32+f]*sh[w][f];
    g_node[node*100+68+lane]=leaky(acc2);
}

// ---------------- 7) pair-BN stats via weighted node moments ----------------
// first half weight = (N-1-i) (ti multiplicity); second half weight = i (tj mult.)
__global__ void k_pstats(){
    int f = blockIdx.x; // 0..99
    __shared__ float s[4][256];
    float sa=0,qa=0,sb=0,qb=0;
    for(int i=threadIdx.x;i<NN;i+=256){
        float v=g_node[i*100+f];
        float wa=(float)(NN-1-i), wb=(float)i;
        sa+=wa*v; qa+=wa*v*v; sb+=wb*v; qb+=wb*v*v;
    }
    s[0][threadIdx.x]=sa; s[1][threadIdx.x]=qa; s[2][threadIdx.x]=sb; s[3][threadIdx.x]=qb;
    __syncthreads();
    for(int o=128;o>0;o>>=1){
        if(threadIdx.x<o){
#pragma unroll
            for(int c=0;c<4;c++) s[c][threadIdx.x]+=s[c][threadIdx.x+o];
        }
        __syncthreads();
    }
    if(threadIdx.x==0){
        const float invP = 1.0f/(float)NPAIR;
        float m1=s[0][0]*invP, q1=s[1][0]*invP;
        float m2=s[2][0]*invP, q2=s[3][0]*invP;
        g_m1[f]=m1; g_s1[f]=rsqrtf(q1-m1*m1+EPSV);
        g_m2[f]=m2; g_s2[f]=rsqrtf(q2-m2*m2+EPSV);
    }
}

// ---------------- 8) fold BN into W1: W1p[f][o], folded bias c[o] ----------------
__global__ void k_w1p(const float* __restrict__ lw1, const float* __restrict__ lb1,
                      const float* __restrict__ lbng, const float* __restrict__ lbnb){
    for(int t=threadIdx.x;t<6400;t+=256){
        int o=t&31, f=t>>5;
        float sc = (f<100)? lbng[f]*g_s1[f] : lbng[f]*g_s2[f-100];
        g_W1p[t] = lw1[o*200+f]*sc;
    }
    __syncthreads();
    if (threadIdx.x<32){
        int o=threadIdx.x;
        float c=lb1[o];
        for(int f=0;f<200;f++){
            float m  = (f<100)? g_m1[f] : g_m2[f-100];
            float sc = (f<100)? lbng[f]*g_s1[f] : lbng[f]*g_s2[f-100];
            c += lw1[o*200+f]*(lbnb[f]-m*sc);
        }
        g_c[o]=c;
    }
}

// ---------------- 9) per-node projections A (with c folded) and B ----------------
__global__ void k_ab(){
    __shared__ float srow[8][100];
    int w=threadIdx.x>>5, lane=threadIdx.x&31;
    int node = blockIdx.x*8+w;
    for(int f=lane;f<100;f+=32) srow[w][f]=g_node[node*100+f];
    __syncwarp();
    float a=g_c[lane], b=0.f;
    for(int f=0;f<100;f++){
        float v=srow[w][f];
        a += v*g_W1p[f*32+lane];
        b += v*g_W1p[(100+f)*32+lane];
    }
    g_A[node*32+lane]=a;
    g_B[node*32+lane]=b;
}

// ---------------- 10) the big pair kernel: 2 pairs/thread ----------------
__global__ void __launch_bounds__(256) k_pairs(const float* __restrict__ lw2,
                                               const float* __restrict__ lb2,
                                               const float* __restrict__ lw3,
                                               const float* __restrict__ lb3,
                                               float* __restrict__ out){
    __shared__ float sW2[1024], sb2[32], sW3[64], sb3[2];
    for(int t=threadIdx.x;t<1024;t+=256) sW2[t]=lw2[t];
    if(threadIdx.x<32) sb2[threadIdx.x]=lb2[threadIdx.x];
    if(threadIdx.x<64) sW3[threadIdx.x]=lw3[threadIdx.x];
    if(threadIdx.x<2)  sb3[threadIdx.x]=lb3[threadIdx.x];
    __syncthreads();

    int tid = blockIdx.x*256+threadIdx.x;
    int p = tid*2;
    if (p >= NPAIR) return;

    // invert p -> (i,j) with i<j ; fp32 sqrt + exact fixup
    int disc = (2*NN-1)*(2*NN-1) - 8*p;     // < 2^24, exact in fp32
    float sq = sqrtf((float)disc);
    int i = (int)(((float)(2*NN-1) - sq)*0.5f);
    if (i<0) i=0; if (i>NN-2) i=NN-2;
    while (i < NN-2 && rowstart(i+1)<=p) i++;
    while (i > 0    && rowstart(i)  > p) i--;
    int j = p - rowstart(i) + i + 1;
    int i2=i, j2=j+1;
    if (j2>=NN){ i2=i+1; j2=i2+1; }

    const float4* Ai  = (const float4*)(g_A + i *32);
    const float4* Ai2 = (const float4*)(g_A + i2*32);
    const float4* Bj  = (const float4*)(g_B + j *32);
    const float4* Bj2 = (const float4*)(g_B + j2*32);

    float h1a[32], h1b[32];
#pragma unroll
    for(int f=0;f<8;f++){
        float4 a  = Ai[f],  bb = Bj[f];
        float4 a2 = Ai2[f], b2v= Bj2[f];
        h1a[f*4+0]=leaky(a.x+bb.x);  h1a[f*4+1]=leaky(a.y+bb.y);
        h1a[f*4+2]=leaky(a.z+bb.z);  h1a[f*4+3]=leaky(a.w+bb.w);
        h1b[f*4+0]=leaky(a2.x+b2v.x); h1b[f*4+1]=leaky(a2.y+b2v.y);
        h1b[f*4+2]=leaky(a2.z+b2v.z); h1b[f*4+3]=leaky(a2.w+b2v.w);
    }

    float y0a=sb3[0], y1a=sb3[1], y0b=sb3[0], y1b=sb3[1];
#pragma unroll
    for(int o=0;o<32;o++){
        float aa=sb2[o], ab=sb2[o];
#pragma unroll
        for(int f=0;f<32;f++){
            float w=sW2[o*32+f];
            aa+=w*h1a[f]; ab+=w*h1b[f];
        }
        float h2a=leaky(aa), h2b=leaky(ab);
        float w30=sW3[o], w31=sW3[32+o];
        y0a+=h2a*w30; y1a+=h2a*w31;
        y0b+=h2b*w30; y1b+=h2b*w31;
    }
    *((float4*)(out + (size_t)p*2)) = make_float4(y0a,y1a,y0b,y1b);
}

// ---------------- launch ----------------
extern "C" void kernel_launch(void* const* d_in, const int* in_sizes, int n_in,
                              void* d_out, int out_size){
    const float* feat   = (const float*)d_in[0];
    const float* bn_g   = (const float*)d_in[1];
    const float* bn_b   = (const float*)d_in[2];
    const float* ec1_w1 = (const float*)d_in[3];
    const float* ec1_b1 = (const float*)d_in[4];
    const float* ec1_w2 = (const float*)d_in[5];
    const float* ec1_b2 = (const float*)d_in[6];
    const float* ec2_w1 = (const float*)d_in[7];
    const float* ec2_b1 = (const float*)d_in[8];
    const float* ec2_w2 = (const float*)d_in[9];
    const float* ec2_b2 = (const float*)d_in[10];
    const float* lbn_g  = (const float*)d_in[11];
    const float* lbn_b  = (const float*)d_in[12];
    const float* l_w1   = (const float*)d_in[13];
    const float* l_b1   = (const float*)d_in[14];
    const float* l_w2   = (const float*)d_in[15];
    const float* l_b2   = (const float*)d_in[16];
    const float* l_w3   = (const float*)d_in[17];
    const float* l_b3   = (const float*)d_in[18];
    float* out = (float*)d_out;

    k_bn_stats <<<36, 256>>>(feat);
    k_transpose<<<36, 256>>>(ec1_w1, ec2_w1);
    k_norm     <<<(NN*D_IN+255)/256, 256>>>(feat, bn_g, bn_b, out + (size_t)2*NPAIR);
    k_knn      <<<NN/8, 256>>>();
    k_edge1    <<<NN/8, 256>>>(ec1_b1, ec1_w2, ec1_b2);
    k_edge2    <<<NN/8, 256>>>(ec2_b1, ec2_w2, ec2_b2);
    k_pstats   <<<100, 256>>>();
    k_w1p      <<<1, 256>>>(l_w1, l_b1, lbn_g, lbn_b);
    k_ab       <<<NN/8, 256>>>();
    k_pairs    <<<(NPAIR/2+255)/256, 256>>>(l_w2, l_b2, l_w3, l_b3, out);
}